// round 14
// baseline (speedup 1.0000x reference)
#include <cuda_runtime.h>
#include <cuda_fp16.h>
#include <mma.h>
#include <math.h>

using namespace nvcuda;

typedef unsigned long long ull;
typedef unsigned int uint;

// ---------------- problem constants ----------------
#define C 64
#define NTOT 310000
#define TOTAL_E 6480000
#define TOTAL_S 810000

__constant__ int c_EOFF[16] = {0,400000,1200000,2000000,2320000,2480000,3280000,
                               4080000,4400000,4560000,5360000,5680000,5840000,
                               6160000,6320000,6480000};
__constant__ int c_SOFF[16] = {0,50000,150000,250000,290000,310000,410000,510000,
                               550000,570000,670000,710000,730000,770000,790000,810000};
// gw/10000 -> pair index (all SOFF are multiples of 10000)
__constant__ char c_KLUT[81] = {
    0,0,0,0,0,
    1,1,1,1,1,1,1,1,1,1,
    2,2,2,2,2,2,2,2,2,2,
    3,3,3,3,
    4,4,
    5,5,5,5,5,5,5,5,5,5,
    6,6,6,6,6,6,6,6,6,6,
    7,7,7,7,
    8,8,
    9,9,9,9,9,9,9,9,9,9,
    10,10,10,10,
    11,11,
    12,12,12,12,
    13,13,
    14,14};
// source-rank feature offset (rows) per pair
__constant__ int c_XOFFI[15] = {0,50000,150000,250000,290000, 0,0,0,0,
                                50000,50000,50000, 150000,150000, 250000};
// gemm block schedule: heavy ranks first (128 rows/block)
__constant__ int c_GB[6] = {0,157,470,1252,2034,2425};
__constant__ int c_GJ[5] = {4,3,2,1,0};
__constant__ int c_JN[5]  = {50000,100000,100000,40000,20000};
__constant__ int c_JXO[5] = {0,50000,150000,250000,290000};
__constant__ int c_NPJ[5] = {1,2,3,4,5};
__constant__ int c_PAIRK[5][5] = {{0,0,0,0,0},{1,5,0,0,0},{2,6,9,0,0},
                                  {3,7,10,12,0},{4,8,11,13,14}};

// ---------------- device scratch ----------------
__device__ float  g_Xa[(size_t)NTOT*C];    // fp32 features A (pooling / L2 out)
__device__ float  g_Xb[(size_t)NTOT*C];    // fp32 features B (L1 out, L2 residual)
__device__ __half g_Xh[(size_t)NTOT*C];    // fp16 gather mirror (40MB)
__device__ __half g_Sh[(size_t)TOTAL_S*C]; // aggregated messages fp16 (104MB)
__device__ __half g_Wh[45*4096];           // fp16 weights
__device__ int2   g_edge[TOTAL_E];         // packed (col*128 bytes, half2(v,v))
__device__ int    g_rowptr[TOTAL_S];
__device__ float  g_sum[320];
__device__ float  g_sq[320];
__device__ int    g_mx[320];
__device__ int    g_mn[320];
__device__ float  g_pooled[1284];
__device__ float  g_h1[512];

// ---------------- helpers ----------------
__device__ __forceinline__ int fenc(float f) {
    int i = __float_as_int(f);
    return i >= 0 ? i : (i ^ 0x7fffffff);
}
__device__ __forceinline__ float fdec(int i) {
    return __int_as_float(i >= 0 ? i : (i ^ 0x7fffffff));
}

// ---------------- fused prep: pack edges + rowptr ---------------------------
// edge.x = col*128 (byte offset of the source row), edge.y = half2(val,val)
__device__ __forceinline__ int val2h2(float v) {
    __half2 h = __half2half2(__float2half(v));
    return *(int*)&h;
}
__global__ void k_prep(const int* __restrict__ rows, const int* __restrict__ cols,
                       const float* __restrict__ vals) {
    int t = blockIdx.x * blockDim.x + threadIdx.x;
    int e0 = t * 4;
    if (e0 >= TOTAL_E) return;

    int4 c4 = *(const int4*)(cols + e0);
    float4 v4 = *(const float4*)(vals + e0);
    int4 p0 = make_int4(c4.x << 7, val2h2(v4.x), c4.y << 7, val2h2(v4.y));
    int4 p1 = make_int4(c4.z << 7, val2h2(v4.z), c4.w << 7, val2h2(v4.w));
    *(int4*)(g_edge + e0)     = p0;
    *(int4*)(g_edge + e0 + 2) = p1;

    // rowptr mark
    int k = 0;
    while (e0 >= c_EOFF[k + 1]) ++k;
    int le0 = e0 - c_EOFF[k];
    int Ek = c_EOFF[k + 1] - c_EOFF[k];
    int Nj = c_SOFF[k + 1] - c_SOFF[k];
    int4 r4 = *(const int4*)(rows + e0);
    int prev = (le0 > 0) ? __ldg(rows + e0 - 1) : -1;
    int* w = g_rowptr + c_SOFF[k];
    int rr[4] = {r4.x, r4.y, r4.z, r4.w};
    #pragma unroll
    for (int q = 0; q < 4; ++q) {
        int r = rr[q];
        if (r > prev)
            for (int x = prev + 1; x <= r; ++x) w[x] = le0 + q;
        prev = r;
    }
    if (le0 + 4 >= Ek)
        for (int x = prev + 1; x < Nj; ++x) w[x] = Ek;
}

__global__ void k_wconv(const float* __restrict__ W) {
    int i = blockIdx.x * blockDim.x + threadIdx.x;
    if (i < 45 * 4096) g_Wh[i] = __float2half(__ldg(W + i));
}
// concat inputs -> g_Xh (fp16)
__global__ void k_xh(const float4* __restrict__ x0, const float4* __restrict__ x1,
                     const float4* __restrict__ x2, const float4* __restrict__ x3,
                     const float4* __restrict__ x4) {
    const int B1 = 800000, B2 = 2400000, B3 = 4000000, B4 = 4640000, B5 = 4960000;
    uint2* Xh = (uint2*)g_Xh;
    for (int i = blockIdx.x * blockDim.x + threadIdx.x; i < B5;
         i += gridDim.x * blockDim.x) {
        float4 v;
        if      (i < B1) v = __ldg(x0 + i);
        else if (i < B2) v = __ldg(x1 + (i - B1));
        else if (i < B3) v = __ldg(x2 + (i - B2));
        else if (i < B4) v = __ldg(x3 + (i - B3));
        else             v = __ldg(x4 + (i - B4));
        __half2 h0 = __floats2half2_rn(v.x, v.y);
        __half2 h1 = __floats2half2_rn(v.z, v.w);
        uint2 u;
        u.x = *(uint*)&h0; u.y = *(uint*)&h1;
        Xh[i] = u;
    }
}

// ---------------- sparse aggregation: warp owns 4 rows, HFMA2 accum ---------
__device__ __forceinline__ void agg_one(const int2* __restrict__ pedge, int e,
                                        const char* __restrict__ srcb, int laneB,
                                        __half2& a0) {
    int2 ed = __ldcs(pedge + e);
    uint hv = *(const uint*)(srcb + (size_t)(unsigned)ed.x + laneB);
    a0 = __hfma2(*(__half2*)&ed.y, *(__half2*)&hv, a0);
}
template<int NP>
__device__ __forceinline__ void agg_pairs(const int2* __restrict__ pedge, int e,
                                          const char* __restrict__ srcb, int laneB,
                                          __half2& a0, __half2& a1) {
    int4 ed[NP];
    #pragma unroll
    for (int t = 0; t < NP; ++t)
        ed[t] = __ldcs((const int4*)(pedge + e) + t);
    uint hv[2 * NP];
    #pragma unroll
    for (int t = 0; t < NP; ++t) {
        hv[2 * t]     = *(const uint*)(srcb + (size_t)(unsigned)ed[t].x + laneB);
        hv[2 * t + 1] = *(const uint*)(srcb + (size_t)(unsigned)ed[t].z + laneB);
    }
    #pragma unroll
    for (int t = 0; t < NP; ++t) {
        a0 = __hfma2(*(__half2*)&ed[t].y, *(__half2*)&hv[2 * t], a0);
        a1 = __hfma2(*(__half2*)&ed[t].w, *(__half2*)&hv[2 * t + 1], a1);
    }
}

__global__ void __launch_bounds__(256)
k_agg(const int2* __restrict__ edge) {
    int wq = blockIdx.x * 8 + (threadIdx.x >> 5);   // row-quad id
    if (wq >= TOTAL_S / 4) return;
    int gw = wq * 4;                                // first row
    int k = c_KLUT[gw / 10000];
    int r  = gw - c_SOFF[k];
    int Nj = c_SOFF[k + 1] - c_SOFF[k];
    int Ek = c_EOFF[k + 1] - c_EOFF[k];
    int laneB = (threadIdx.x & 31) * 4;             // byte offset within row

    const int*  rp    = g_rowptr + c_SOFF[k];
    const int2* pedge = edge + c_EOFF[k];
    const char* srcb  = (const char*)(g_Xh + (size_t)c_XOFFI[k] * C);

    int4 b4 = *(const int4*)(rp + r);
    int b5 = (r + 4 < Nj) ? __ldg(rp + r + 4) : Ek;
    int bs[5] = {b4.x, b4.y, b4.z, b4.w, b5};

    __half* Sout = g_Sh + (size_t)gw * C + (threadIdx.x & 31) * 2;
    #pragma unroll
    for (int q = 0; q < 4; ++q) {
        int es = bs[q], ee = bs[q + 1];
        __half2 a0 = __half2half2(__ushort_as_half(0));
        __half2 a1 = a0;
        int e = es;
        if ((e & 1) && e < ee) { agg_one(pedge, e, srcb, laneB, a0); ++e; }
        while (e + 8 <= ee) { agg_pairs<4>(pedge, e, srcb, laneB, a0, a1); e += 8; }
        if (e + 4 <= ee)    { agg_pairs<2>(pedge, e, srcb, laneB, a0, a1); e += 4; }
        if (e + 2 <= ee)    { agg_pairs<1>(pedge, e, srcb, laneB, a0, a1); e += 2; }
        if (e < ee)         { agg_one(pedge, e, srcb, laneB, a0); }
        // combine the two half2 accumulators in fp32, store as half2
        float2 f0 = __half22float2(a0);
        float2 f1 = __half22float2(a1);
        __half2 h = __floats2half2_rn(f0.x + f1.x, f0.y + f1.y);
        __stcs((uint*)(Sout + (size_t)q * C), *(uint*)&h);
    }
}

// ---------------- tensor-core GEMM + residual + relu ------------------------
// software pipeline: next pair's S/W tiles staged in registers during the mma.
#define SS_LD 72
#define SO_LD 68
__global__ void __launch_bounds__(256)
k_gemm(const __half* __restrict__ Whl, const float* __restrict__ residBase,
       float* __restrict__ dstX, int resid, int wF32, int wF16) {
    extern __shared__ char smraw[];
    __half* sS = (__half*)smraw;                       // 128 x 72 half
    __half* sW = (__half*)(smraw + 128 * SS_LD * 2);   // 64 x 72 half
    float*  sO = (float*)smraw;                        // epilogue: 128 x 68 f32

    int b = blockIdx.x;
    int ji = 0;
    while (b >= c_GB[ji + 1]) ++ji;
    int j = c_GJ[ji];
    int rowBase = (b - c_GB[ji]) * 128;
    int Nj = c_JN[j];

    int tid  = threadIdx.x;
    int warp = tid >> 5;

    int sr[8], sc[8], wr[4], wc[4];
    #pragma unroll
    for (int i = 0; i < 8; ++i) {
        int t = tid + i * 256;
        sr[i] = t >> 4; sc[i] = (t & 15) * 4;
    }
    #pragma unroll
    for (int i = 0; i < 4; ++i) {
        int t = tid + i * 256;
        wr[i] = t >> 4; wc[i] = (t & 15) * 4;
    }

    wmma::fragment<wmma::accumulator, 16, 16, 16, float> acc[4];
    #pragma unroll
    for (int n = 0; n < 4; ++n) wmma::fill_fragment(acc[n], 0.f);

    int np = c_NPJ[j];
    uint2 sreg[8], wreg[4];

    {
        int k = c_PAIRK[j][0];
        const __half* W = Whl + k * 4096;
        const __half* S = g_Sh + (size_t)(c_SOFF[k] + rowBase) * C;
        #pragma unroll
        for (int i = 0; i < 8; ++i) {
            sreg[i] = make_uint2(0, 0);
            if (rowBase + sr[i] < Nj)
                sreg[i] = __ldcs((const uint2*)(S + (size_t)sr[i] * C + sc[i]));
        }
        #pragma unroll
        for (int i = 0; i < 4; ++i)
            wreg[i] = *(const uint2*)(W + wr[i] * C + wc[i]);
    }

    for (int p = 0; p < np; ++p) {
        #pragma unroll
        for (int i = 0; i < 8; ++i)
            *(uint2*)(sS + sr[i] * SS_LD + sc[i]) = sreg[i];
        #pragma unroll
        for (int i = 0; i < 4; ++i)
            *(uint2*)(sW + wr[i] * SS_LD + wc[i]) = wreg[i];
        __syncthreads();

        if (p + 1 < np) {
            int k = c_PAIRK[j][p + 1];
            const __half* W = Whl + k * 4096;
            const __half* S = g_Sh + (size_t)(c_SOFF[k] + rowBase) * C;
            #pragma unroll
            for (int i = 0; i < 8; ++i) {
                sreg[i] = make_uint2(0, 0);
                if (rowBase + sr[i] < Nj)
                    sreg[i] = __ldcs((const uint2*)(S + (size_t)sr[i] * C + sc[i]));
            }
            #pragma unroll
            for (int i = 0; i < 4; ++i)
                wreg[i] = *(const uint2*)(W + wr[i] * C + wc[i]);
        }

        #pragma unroll
        for (int k0 = 0; k0 < 64; k0 += 16) {
            wmma::fragment<wmma::matrix_a, 16, 16, 16, __half, wmma::row_major> af;
            wmma::load_matrix_sync(af, sS + warp * 16 * SS_LD + k0, SS_LD);
            #pragma unroll
            for (int n = 0; n < 4; ++n) {
                wmma::fragment<wmma::matrix_b, 16, 16, 16, __half, wmma::row_major> bf;
                wmma::load_matrix_sync(bf, sW + k0 * SS_LD + n * 16, SS_LD);
                wmma::mma_sync(acc[n], af, bf, acc[n]);
            }
        }
        __syncthreads();
    }

    #pragma unroll
    for (int n = 0; n < 4; ++n)
        wmma::store_matrix_sync(sO + warp * 16 * SO_LD + n * 16, acc[n], SO_LD,
                                wmma::mem_row_major);
    __syncthreads();

    float* Xd = dstX + (size_t)c_JXO[j] * C;
    const float* Xr = residBase + (size_t)c_JXO[j] * C;
    __half* Xh = g_Xh + (size_t)c_JXO[j] * C;
    #pragma unroll
    for (int t = tid; t < 2048; t += 256) {
        int r = t >> 4, c4 = (t & 15) * 4;
        int gr = rowBase + r;
        if (gr < Nj) {
            float4 o = *(const float4*)(sO + r * SO_LD + c4);
            if (resid) {
                float4 x = *(const float4*)(Xr + (size_t)gr * C + c4);
                o.x += x.x; o.y += x.y; o.z += x.z; o.w += x.w;
            }
            o.x = fmaxf(o.x, 0.f); o.y = fmaxf(o.y, 0.f);
            o.z = fmaxf(o.z, 0.f); o.w = fmaxf(o.w, 0.f);
            if (wF32)
                __stcs((float4*)(Xd + (size_t)gr * C + c4), o);
            if (wF16) {
                __half2 h0 = __floats2half2_rn(o.x, o.y);
                __half2 h1 = __floats2half2_rn(o.z, o.w);
                uint2 u;
                u.x = *(uint*)&h0; u.y = *(uint*)&h1;
                *(uint2*)(Xh + (size_t)gr * C + c4) = u;
            }
        }
    }
}

// ---------------- pooling (reads g_Xa) ----------------
__global__ void k_pool_init() {
    int t = threadIdx.x;
    if (t < 320) {
        g_sum[t] = 0.f; g_sq[t] = 0.f;
        g_mx[t] = 0x80000000; g_mn[t] = 0x7fffffff;
    }
}
__global__ void k_pool() {
    int rank = blockIdx.y;
    int c = threadIdx.x & 63;
    int rg = threadIdx.x >> 6;
    int Nr = c_JN[rank];
    const float* base = g_Xa + (size_t)c_JXO[rank] * C;
    float s = 0.f, sq = 0.f, mx = -3.402823466e38f, mn = 3.402823466e38f;
    for (int r = blockIdx.x * 4 + rg; r < Nr; r += gridDim.x * 4) {
        float v = base[(size_t)r * C + c];
        s += v; sq = fmaf(v, v, sq);
        mx = fmaxf(mx, v); mn = fminf(mn, v);
    }
    int o = rank * 64 + c;
    atomicAdd(&g_sum[o], s);
    atomicAdd(&g_sq[o], sq);
    atomicMax(&g_mx[o], fenc(mx));
    atomicMin(&g_mn[o], fenc(mn));
}
__global__ void k_pool_fin(const float* __restrict__ gf) {
    int idx = blockIdx.x * blockDim.x + threadIdx.x;
    if (idx >= 1284) return;
    if (idx >= 1280) { g_pooled[idx] = gf[idx - 1280]; return; }
    int rank = idx >> 8;
    int part = (idx >> 6) & 3;
    int c = idx & 63;
    int o = rank * 64 + c;
    float Nr = (float)c_JN[rank];
    float val;
    if (part == 0) val = g_sum[o] / Nr;
    else if (part == 1) {
        float m = g_sum[o] / Nr;
        float var = g_sq[o] / Nr - m * m;
        var = fmaxf(var, 0.f);
        if (var == 0.f) var = 1e-6f;
        val = sqrtf(var);
    } else if (part == 2) val = fdec(g_mx[o]);
    else val = fdec(g_mn[o]);
    g_pooled[idx] = val;
}

// ---------------- MLP head ----------------
__global__ void k_fc1(const float* __restrict__ w, const float* __restrict__ b) {
    __shared__ float p[1284];
    __shared__ float red[256];
    for (int i = threadIdx.x; i < 1284; i += 256) p[i] = g_pooled[i];
    __syncthreads();
    int lane = threadIdx.x & 31;
    int rp = threadIdx.x >> 5;
    int o = blockIdx.x * 32 + lane;
    float s = 0.f;
    for (int i = rp; i < 1284; i += 8) s = fmaf(p[i], w[(size_t)i * 512 + o], s);
    red[threadIdx.x] = s;
    __syncthreads();
    if (rp == 0) {
        float t = s;
        #pragma unroll
        for (int q = 1; q < 8; ++q) t += red[q * 32 + lane];
        t += b[o];
        g_h1[o] = fmaxf(t, 0.f);
    }
}
__global__ void k_tail(const float* __restrict__ w2, const float* __restrict__ b2,
                       const float* __restrict__ w3, const float* __restrict__ b3,
                       const float* __restrict__ w4, const float* __restrict__ b4,
                       float* __restrict__ out) {
    __shared__ float h2[128];
    __shared__ float h3[64];
    int tid = threadIdx.x;
    {
        float s = b2[tid];
        for (int i = 0; i < 512; ++i) s = fmaf(g_h1[i], w2[(size_t)i * 128 + tid], s);
        h2[tid] = fmaxf(s, 0.f);
    }
    __syncthreads();
    if (tid < 64) {
        float s = b3[tid];
        for (int i = 0; i < 128; ++i) s = fmaf(h2[i], w3[(size_t)i * 64 + tid], s);
        h3[tid] = fmaxf(s, 0.f);
    }
    __syncthreads();
    if (tid < 2) {
        float s = b4[tid];
        for (int i = 0; i < 64; ++i) s = fmaf(h3[i], w4[(size_t)i * 2 + tid], s);
        out[tid] = (tid == 0) ? s : s * s;
    }
}

// ---------------- host launcher ----------------
extern "C" void kernel_launch(void* const* d_in, const int* in_sizes, int n_in,
                              void* d_out, int out_size) {
    const float* x0 = (const float*)d_in[0];
    const float* x1 = (const float*)d_in[1];
    const float* x2 = (const float*)d_in[2];
    const float* x3 = (const float*)d_in[3];
    const float* x4 = (const float*)d_in[4];
    const int*   rows = (const int*)d_in[5];
    const int*   cols = (const int*)d_in[6];
    const float* vals = (const float*)d_in[7];
    const float* gf   = (const float*)d_in[8];
    const float* Whmc = (const float*)d_in[9];
    const float* fc1w = (const float*)d_in[10];
    const float* fc1b = (const float*)d_in[11];
    const float* fc2w = (const float*)d_in[12];
    const float* fc2b = (const float*)d_in[13];
    const float* fc3w = (const float*)d_in[14];
    const float* fc3b = (const float*)d_in[15];
    const float* fc4w = (const float*)d_in[16];
    const float* fc4b = (const float*)d_in[17];
    float* out = (float*)d_out;

    const int SMEM_BYTES = 34816;
    cudaFuncSetAttribute(k_gemm, cudaFuncAttributeMaxDynamicSharedMemorySize,
                         SMEM_BYTES);

    float *h_Xa = nullptr, *h_Xb = nullptr;
    int2* h_edge = nullptr;
    __half* h_Wh = nullptr;
    cudaGetSymbolAddress((void**)&h_Xa, g_Xa);
    cudaGetSymbolAddress((void**)&h_Xb, g_Xb);
    cudaGetSymbolAddress((void**)&h_edge, g_edge);
    cudaGetSymbolAddress((void**)&h_Wh, g_Wh);

    k_xh<<<4096, 256>>>((const float4*)x0, (const float4*)x1, (const float4*)x2,
                        (const float4*)x3, (const float4*)x4);
    k_prep<<<6329, 256>>>(rows, cols, vals);
    k_wconv<<<720, 256>>>(Whmc);

    const int AGG_BLOCKS = (TOTAL_S / 4 + 7) / 8;   // 25313
    // L0: Xh(inputs) -> Xh only
    k_agg<<<AGG_BLOCKS, 256>>>(h_edge);
    k_gemm<<<2425, 256, SMEM_BYTES>>>(h_Wh,           h_Xa, h_Xa, 0, 0, 1);
    // L1: Xh -> Xb (fp32 residual source) + Xh
    k_agg<<<AGG_BLOCKS, 256>>>(h_edge);
    k_gemm<<<2425, 256, SMEM_BYTES>>>(h_Wh + 15*4096, h_Xa, h_Xb, 0, 1, 1);
    // L2: Xh -> Xa (fp32 pooling), residual from Xb, no fp16 out
    k_agg<<<AGG_BLOCKS, 256>>>(h_edge);
    k_gemm<<<2425, 256, SMEM_BYTES>>>(h_Wh + 30*4096, h_Xb, h_Xa, 1, 1, 0);

    k_pool_init<<<1, 320>>>();
    k_pool<<<dim3(256, 5), 256>>>();
    k_pool_fin<<<6, 256>>>(gf);
    k_fc1<<<16, 256>>>(fc1w, fc1b);
    k_tail<<<1, 128>>>(fc2w, fc2b, fc3w, fc3b, fc4w, fc4b, out);
}

// round 15
// speedup vs baseline: 1.1020x; 1.1020x over previous
#include <cuda_runtime.h>
#include <cuda_fp16.h>
#include <mma.h>
#include <math.h>

using namespace nvcuda;

typedef unsigned long long ull;
typedef unsigned int uint;

// ---------------- problem constants ----------------
#define C 64
#define NTOT 310000
#define TOTAL_E 6480000
#define TOTAL_S 810000

__constant__ int c_EOFF[16] = {0,400000,1200000,2000000,2320000,2480000,3280000,
                               4080000,4400000,4560000,5360000,5680000,5840000,
                               6160000,6320000,6480000};
__constant__ int c_SOFF[16] = {0,50000,150000,250000,290000,310000,410000,510000,
                               550000,570000,670000,710000,730000,770000,790000,810000};
// gw/10000 -> pair index (all SOFF are multiples of 10000)
__constant__ char c_KLUT[81] = {
    0,0,0,0,0,
    1,1,1,1,1,1,1,1,1,1,
    2,2,2,2,2,2,2,2,2,2,
    3,3,3,3,
    4,4,
    5,5,5,5,5,5,5,5,5,5,
    6,6,6,6,6,6,6,6,6,6,
    7,7,7,7,
    8,8,
    9,9,9,9,9,9,9,9,9,9,
    10,10,10,10,
    11,11,
    12,12,12,12,
    13,13,
    14,14};
// source-rank feature offset (rows) per pair
__constant__ int c_XOFFI[15] = {0,50000,150000,250000,290000, 0,0,0,0,
                                50000,50000,50000, 150000,150000, 250000};
// gemm block schedule: heavy ranks first (128 rows/block)
__constant__ int c_GB[6] = {0,157,470,1252,2034,2425};
__constant__ int c_GJ[5] = {4,3,2,1,0};
__constant__ int c_JN[5]  = {50000,100000,100000,40000,20000};
__constant__ int c_JXO[5] = {0,50000,150000,250000,290000};
__constant__ int c_NPJ[5] = {1,2,3,4,5};
__constant__ int c_PAIRK[5][5] = {{0,0,0,0,0},{1,5,0,0,0},{2,6,9,0,0},
                                  {3,7,10,12,0},{4,8,11,13,14}};

// ---------------- device scratch ----------------
__device__ float  g_Xa[(size_t)NTOT*C];    // fp32 features A (pooling / L2 out)
__device__ float  g_Xb[(size_t)NTOT*C];    // fp32 features B (L1 out, L2 residual)
__device__ __half g_Xh[(size_t)NTOT*C];    // fp16 gather mirror (40MB)
__device__ __half g_Sh[(size_t)TOTAL_S*C]; // aggregated messages fp16 (104MB)
__device__ __half g_Wh[45*4096];           // fp16 weights
__device__ int2   g_edge[TOTAL_E];         // packed (col*128 bytes, half2(v,v))
__device__ int    g_rowptr[TOTAL_S];
__device__ float  g_sum[320];
__device__ float  g_sq[320];
__device__ int    g_mx[320];
__device__ int    g_mn[320];
__device__ float  g_pooled[1284];
__device__ float  g_h1[512];

// ---------------- helpers ----------------
__device__ __forceinline__ int fenc(float f) {
    int i = __float_as_int(f);
    return i >= 0 ? i : (i ^ 0x7fffffff);
}
__device__ __forceinline__ float fdec(int i) {
    return __int_as_float(i >= 0 ? i : (i ^ 0x7fffffff));
}
__device__ __forceinline__ __half2 h2zero() {
    return __half2half2(__ushort_as_half((unsigned short)0));
}
__device__ __forceinline__ void hfma_e(int vbits, uint hv, __half2& a) {
    a = __hfma2(*(__half2*)&vbits, *(__half2*)&hv, a);
}

// ---------------- fused prep: pack edges + rowptr ---------------------------
// edge.x = col*128 (byte offset of the source row), edge.y = half2(val,val)
__device__ __forceinline__ int val2h2(float v) {
    __half2 h = __half2half2(__float2half(v));
    return *(int*)&h;
}
__global__ void k_prep(const int* __restrict__ rows, const int* __restrict__ cols,
                       const float* __restrict__ vals) {
    int t = blockIdx.x * blockDim.x + threadIdx.x;
    int e0 = t * 4;
    if (e0 >= TOTAL_E) return;

    int4 c4 = *(const int4*)(cols + e0);
    float4 v4 = *(const float4*)(vals + e0);
    int4 p0 = make_int4(c4.x << 7, val2h2(v4.x), c4.y << 7, val2h2(v4.y));
    int4 p1 = make_int4(c4.z << 7, val2h2(v4.z), c4.w << 7, val2h2(v4.w));
    *(int4*)(g_edge + e0)     = p0;
    *(int4*)(g_edge + e0 + 2) = p1;

    // rowptr mark
    int k = 0;
    while (e0 >= c_EOFF[k + 1]) ++k;
    int le0 = e0 - c_EOFF[k];
    int Ek = c_EOFF[k + 1] - c_EOFF[k];
    int Nj = c_SOFF[k + 1] - c_SOFF[k];
    int4 r4 = *(const int4*)(rows + e0);
    int prev = (le0 > 0) ? __ldg(rows + e0 - 1) : -1;
    int* w = g_rowptr + c_SOFF[k];
    int rr[4] = {r4.x, r4.y, r4.z, r4.w};
    #pragma unroll
    for (int q = 0; q < 4; ++q) {
        int r = rr[q];
        if (r > prev)
            for (int x = prev + 1; x <= r; ++x) w[x] = le0 + q;
        prev = r;
    }
    if (le0 + 4 >= Ek)
        for (int x = prev + 1; x < Nj; ++x) w[x] = Ek;
}

__global__ void k_wconv(const float* __restrict__ W) {
    int i = blockIdx.x * blockDim.x + threadIdx.x;
    if (i < 45 * 4096) g_Wh[i] = __float2half(__ldg(W + i));
}
// concat inputs -> g_Xh (fp16)
__global__ void k_xh(const float4* __restrict__ x0, const float4* __restrict__ x1,
                     const float4* __restrict__ x2, const float4* __restrict__ x3,
                     const float4* __restrict__ x4) {
    const int B1 = 800000, B2 = 2400000, B3 = 4000000, B4 = 4640000, B5 = 4960000;
    uint2* Xh = (uint2*)g_Xh;
    for (int i = blockIdx.x * blockDim.x + threadIdx.x; i < B5;
         i += gridDim.x * blockDim.x) {
        float4 v;
        if      (i < B1) v = __ldg(x0 + i);
        else if (i < B2) v = __ldg(x1 + (i - B1));
        else if (i < B3) v = __ldg(x2 + (i - B2));
        else if (i < B4) v = __ldg(x3 + (i - B3));
        else             v = __ldg(x4 + (i - B4));
        __half2 h0 = __floats2half2_rn(v.x, v.y);
        __half2 h1 = __floats2half2_rn(v.z, v.w);
        uint2 u;
        u.x = *(uint*)&h0; u.y = *(uint*)&h1;
        Xh[i] = u;
    }
}

// ---------------- sparse aggregation: smem edge staging ---------------------
// block = 40 rows of one pair (pair sizes all divisible by 40). Phase 1 bulk-
// loads the block's contiguous edge span into smem (coalesced, dependency-
// free). Phase 2: 8 warps x 5 rows; edges via LDS, gathers via LDG, HFMA2.
#define ECAP 1536
__global__ void __launch_bounds__(256)
k_agg(const int2* __restrict__ edge) {
    __shared__ int2 sE[ECAP];
    int b = blockIdx.x;
    int gw0 = b * 40;
    int k = c_KLUT[gw0 / 10000];
    int r0 = gw0 - c_SOFF[k];
    int Nj = c_SOFF[k + 1] - c_SOFF[k];
    int Ek = c_EOFF[k + 1] - c_EOFF[k];

    const int*  rp    = g_rowptr + c_SOFF[k];
    const int2* pedge = edge + c_EOFF[k];
    const char* srcb  = (const char*)(g_Xh + (size_t)c_XOFFI[k] * C);

    int base = __ldg(rp + r0);
    int bend = (r0 + 40 < Nj) ? __ldg(rp + r0 + 40) : Ek;
    int ncap = min(bend - base, ECAP);
    for (int i = threadIdx.x; i < ncap; i += 256)
        sE[i] = __ldcs(pedge + base + i);
    __syncthreads();

    int warp = threadIdx.x >> 5;
    int lane = threadIdx.x & 31;
    int laneB = lane * 4;
    int r = r0 + warp * 5;

    int bs[6];
    #pragma unroll
    for (int i = 0; i < 6; ++i) {
        int rr = r + i;
        bs[i] = (rr < Nj) ? __ldg(rp + rr) : Ek;
    }

    __half* Sout = g_Sh + (size_t)(c_SOFF[k] + r) * C + lane * 2;
    #pragma unroll
    for (int q = 0; q < 5; ++q) {
        int es = bs[q], ee = bs[q + 1];
        __half2 a0 = h2zero(), a1 = h2zero();
        if (ee - base <= ncap) {
            // smem path (local indices)
            int e = es - base, eend = ee - base;
            if ((e & 1) && e < eend) {
                int2 ed = sE[e];
                uint hv = *(const uint*)(srcb + (size_t)(unsigned)ed.x + laneB);
                hfma_e(ed.y, hv, a0);
                ++e;
            }
            while (e + 4 <= eend) {
                int4 ea = *(const int4*)(sE + e);
                int4 eb = *(const int4*)(sE + e + 2);
                uint h0 = *(const uint*)(srcb + (size_t)(unsigned)ea.x + laneB);
                uint h1 = *(const uint*)(srcb + (size_t)(unsigned)ea.z + laneB);
                uint h2 = *(const uint*)(srcb + (size_t)(unsigned)eb.x + laneB);
                uint h3 = *(const uint*)(srcb + (size_t)(unsigned)eb.z + laneB);
                hfma_e(ea.y, h0, a0); hfma_e(ea.w, h1, a1);
                hfma_e(eb.y, h2, a0); hfma_e(eb.w, h3, a1);
                e += 4;
            }
            if (e + 2 <= eend) {
                int4 ea = *(const int4*)(sE + e);
                uint h0 = *(const uint*)(srcb + (size_t)(unsigned)ea.x + laneB);
                uint h1 = *(const uint*)(srcb + (size_t)(unsigned)ea.z + laneB);
                hfma_e(ea.y, h0, a0); hfma_e(ea.w, h1, a1);
                e += 2;
            }
            if (e < eend) {
                int2 ed = sE[e];
                uint hv = *(const uint*)(srcb + (size_t)(unsigned)ed.x + laneB);
                hfma_e(ed.y, hv, a0);
            }
        } else {
            // global fallback (overflowed staging cap; rare)
            for (int e = es; e < ee; ++e) {
                int2 ed = __ldcs(pedge + e);
                uint hv = *(const uint*)(srcb + (size_t)(unsigned)ed.x + laneB);
                hfma_e(ed.y, hv, a0);
            }
        }
        float2 f0 = __half22float2(a0);
        float2 f1 = __half22float2(a1);
        __half2 h = __floats2half2_rn(f0.x + f1.x, f0.y + f1.y);
        __stcs((uint*)Sout, *(uint*)&h);
        Sout += C;
    }
}

// ---------------- tensor-core GEMM + residual + relu ------------------------
// software pipeline: next pair's S/W tiles staged in registers during the mma.
#define SS_LD 72
#define SO_LD 68
__global__ void __launch_bounds__(256)
k_gemm(const __half* __restrict__ Whl, const float* __restrict__ residBase,
       float* __restrict__ dstX, int resid, int wF32, int wF16) {
    extern __shared__ char smraw[];
    __half* sS = (__half*)smraw;                       // 128 x 72 half
    __half* sW = (__half*)(smraw + 128 * SS_LD * 2);   // 64 x 72 half
    float*  sO = (float*)smraw;                        // epilogue: 128 x 68 f32

    int b = blockIdx.x;
    int ji = 0;
    while (b >= c_GB[ji + 1]) ++ji;
    int j = c_GJ[ji];
    int rowBase = (b - c_GB[ji]) * 128;
    int Nj = c_JN[j];

    int tid  = threadIdx.x;
    int warp = tid >> 5;

    int sr[8], sc[8], wr[4], wc[4];
    #pragma unroll
    for (int i = 0; i < 8; ++i) {
        int t = tid + i * 256;
        sr[i] = t >> 4; sc[i] = (t & 15) * 4;
    }
    #pragma unroll
    for (int i = 0; i < 4; ++i) {
        int t = tid + i * 256;
        wr[i] = t >> 4; wc[i] = (t & 15) * 4;
    }

    wmma::fragment<wmma::accumulator, 16, 16, 16, float> acc[4];
    #pragma unroll
    for (int n = 0; n < 4; ++n) wmma::fill_fragment(acc[n], 0.f);

    int np = c_NPJ[j];
    uint2 sreg[8], wreg[4];

    {
        int k = c_PAIRK[j][0];
        const __half* W = Whl + k * 4096;
        const __half* S = g_Sh + (size_t)(c_SOFF[k] + rowBase) * C;
        #pragma unroll
        for (int i = 0; i < 8; ++i) {
            sreg[i] = make_uint2(0, 0);
            if (rowBase + sr[i] < Nj)
                sreg[i] = __ldcs((const uint2*)(S + (size_t)sr[i] * C + sc[i]));
        }
        #pragma unroll
        for (int i = 0; i < 4; ++i)
            wreg[i] = *(const uint2*)(W + wr[i] * C + wc[i]);
    }

    for (int p = 0; p < np; ++p) {
        #pragma unroll
        for (int i = 0; i < 8; ++i)
            *(uint2*)(sS + sr[i] * SS_LD + sc[i]) = sreg[i];
        #pragma unroll
        for (int i = 0; i < 4; ++i)
            *(uint2*)(sW + wr[i] * SS_LD + wc[i]) = wreg[i];
        __syncthreads();

        if (p + 1 < np) {
            int k = c_PAIRK[j][p + 1];
            const __half* W = Whl + k * 4096;
            const __half* S = g_Sh + (size_t)(c_SOFF[k] + rowBase) * C;
            #pragma unroll
            for (int i = 0; i < 8; ++i) {
                sreg[i] = make_uint2(0, 0);
                if (rowBase + sr[i] < Nj)
                    sreg[i] = __ldcs((const uint2*)(S + (size_t)sr[i] * C + sc[i]));
            }
            #pragma unroll
            for (int i = 0; i < 4; ++i)
                wreg[i] = *(const uint2*)(W + wr[i] * C + wc[i]);
        }

        #pragma unroll
        for (int k0 = 0; k0 < 64; k0 += 16) {
            wmma::fragment<wmma::matrix_a, 16, 16, 16, __half, wmma::row_major> af;
            wmma::load_matrix_sync(af, sS + warp * 16 * SS_LD + k0, SS_LD);
            #pragma unroll
            for (int n = 0; n < 4; ++n) {
                wmma::fragment<wmma::matrix_b, 16, 16, 16, __half, wmma::row_major> bf;
                wmma::load_matrix_sync(bf, sW + k0 * SS_LD + n * 16, SS_LD);
                wmma::mma_sync(acc[n], af, bf, acc[n]);
            }
        }
        __syncthreads();
    }

    #pragma unroll
    for (int n = 0; n < 4; ++n)
        wmma::store_matrix_sync(sO + warp * 16 * SO_LD + n * 16, acc[n], SO_LD,
                                wmma::mem_row_major);
    __syncthreads();

    float* Xd = dstX + (size_t)c_JXO[j] * C;
    const float* Xr = residBase + (size_t)c_JXO[j] * C;
    __half* Xh = g_Xh + (size_t)c_JXO[j] * C;
    #pragma unroll
    for (int t = tid; t < 2048; t += 256) {
        int r = t >> 4, c4 = (t & 15) * 4;
        int gr = rowBase + r;
        if (gr < Nj) {
            float4 o = *(const float4*)(sO + r * SO_LD + c4);
            if (resid) {
                float4 x = *(const float4*)(Xr + (size_t)gr * C + c4);
                o.x += x.x; o.y += x.y; o.z += x.z; o.w += x.w;
            }
            o.x = fmaxf(o.x, 0.f); o.y = fmaxf(o.y, 0.f);
            o.z = fmaxf(o.z, 0.f); o.w = fmaxf(o.w, 0.f);
            if (wF32)
                __stcs((float4*)(Xd + (size_t)gr * C + c4), o);
            if (wF16) {
                __half2 h0 = __floats2half2_rn(o.x, o.y);
                __half2 h1 = __floats2half2_rn(o.z, o.w);
                uint2 u;
                u.x = *(uint*)&h0; u.y = *(uint*)&h1;
                *(uint2*)(Xh + (size_t)gr * C + c4) = u;
            }
        }
    }
}

// ---------------- pooling (reads g_Xa) ----------------
__global__ void k_pool_init() {
    int t = threadIdx.x;
    if (t < 320) {
        g_sum[t] = 0.f; g_sq[t] = 0.f;
        g_mx[t] = 0x80000000; g_mn[t] = 0x7fffffff;
    }
}
__global__ void k_pool() {
    int rank = blockIdx.y;
    int c = threadIdx.x & 63;
    int rg = threadIdx.x >> 6;
    int Nr = c_JN[rank];
    const float* base = g_Xa + (size_t)c_JXO[rank] * C;
    float s = 0.f, sq = 0.f, mx = -3.402823466e38f, mn = 3.402823466e38f;
    for (int r = blockIdx.x * 4 + rg; r < Nr; r += gridDim.x * 4) {
        float v = base[(size_t)r * C + c];
        s += v; sq = fmaf(v, v, sq);
        mx = fmaxf(mx, v); mn = fminf(mn, v);
    }
    int o = rank * 64 + c;
    atomicAdd(&g_sum[o], s);
    atomicAdd(&g_sq[o], sq);
    atomicMax(&g_mx[o], fenc(mx));
    atomicMin(&g_mn[o], fenc(mn));
}
__global__ void k_pool_fin(const float* __restrict__ gf) {
    int idx = blockIdx.x * blockDim.x + threadIdx.x;
    if (idx >= 1284) return;
    if (idx >= 1280) { g_pooled[idx] = gf[idx - 1280]; return; }
    int rank = idx >> 8;
    int part = (idx >> 6) & 3;
    int c = idx & 63;
    int o = rank * 64 + c;
    float Nr = (float)c_JN[rank];
    float val;
    if (part == 0) val = g_sum[o] / Nr;
    else if (part == 1) {
        float m = g_sum[o] / Nr;
        float var = g_sq[o] / Nr - m * m;
        var = fmaxf(var, 0.f);
        if (var == 0.f) var = 1e-6f;
        val = sqrtf(var);
    } else if (part == 2) val = fdec(g_mx[o]);
    else val = fdec(g_mn[o]);
    g_pooled[idx] = val;
}

// ---------------- MLP head ----------------
__global__ void k_fc1(const float* __restrict__ w, const float* __restrict__ b) {
    __shared__ float p[1284];
    __shared__ float red[256];
    for (int i = threadIdx.x; i < 1284; i += 256) p[i] = g_pooled[i];
    __syncthreads();
    int lane = threadIdx.x & 31;
    int rp = threadIdx.x >> 5;
    int o = blockIdx.x * 32 + lane;
    float s = 0.f;
    for (int i = rp; i < 1284; i += 8) s = fmaf(p[i], w[(size_t)i * 512 + o], s);
    red[threadIdx.x] = s;
    __syncthreads();
    if (rp == 0) {
        float t = s;
        #pragma unroll
        for (int q = 1; q < 8; ++q) t += red[q * 32 + lane];
        t += b[o];
        g_h1[o] = fmaxf(t, 0.f);
    }
}
__global__ void k_tail(const float* __restrict__ w2, const float* __restrict__ b2,
                       const float* __restrict__ w3, const float* __restrict__ b3,
                       const float* __restrict__ w4, const float* __restrict__ b4,
                       float* __restrict__ out) {
    __shared__ float h2[128];
    __shared__ float h3[64];
    int tid = threadIdx.x;
    {
        float s = b2[tid];
        for (int i = 0; i < 512; ++i) s = fmaf(g_h1[i], w2[(size_t)i * 128 + tid], s);
        h2[tid] = fmaxf(s, 0.f);
    }
    __syncthreads();
    if (tid < 64) {
        float s = b3[tid];
        for (int i = 0; i < 128; ++i) s = fmaf(h2[i], w3[(size_t)i * 64 + tid], s);
        h3[tid] = fmaxf(s, 0.f);
    }
    __syncthreads();
    if (tid < 2) {
        float s = b4[tid];
        for (int i = 0; i < 64; ++i) s = fmaf(h3[i], w4[(size_t)i * 2 + tid], s);
        out[tid] = (tid == 0) ? s : s * s;
    }
}

// ---------------- host launcher ----------------
extern "C" void kernel_launch(void* const* d_in, const int* in_sizes, int n_in,
                              void* d_out, int out_size) {
    const float* x0 = (const float*)d_in[0];
    const float* x1 = (const float*)d_in[1];
    const float* x2 = (const float*)d_in[2];
    const float* x3 = (const float*)d_in[3];
    const float* x4 = (const float*)d_in[4];
    const int*   rows = (const int*)d_in[5];
    const int*   cols = (const int*)d_in[6];
    const float* vals = (const float*)d_in[7];
    const float* gf   = (const float*)d_in[8];
    const float* Whmc = (const float*)d_in[9];
    const float* fc1w = (const float*)d_in[10];
    const float* fc1b = (const float*)d_in[11];
    const float* fc2w = (const float*)d_in[12];
    const float* fc2b = (const float*)d_in[13];
    const float* fc3w = (const float*)d_in[14];
    const float* fc3b = (const float*)d_in[15];
    const float* fc4w = (const float*)d_in[16];
    const float* fc4b = (const float*)d_in[17];
    float* out = (float*)d_out;

    const int SMEM_BYTES = 34816;
    cudaFuncSetAttribute(k_gemm, cudaFuncAttributeMaxDynamicSharedMemorySize,
                         SMEM_BYTES);

    float *h_Xa = nullptr, *h_Xb = nullptr;
    int2* h_edge = nullptr;
    __half* h_Wh = nullptr;
    cudaGetSymbolAddress((void**)&h_Xa, g_Xa);
    cudaGetSymbolAddress((void**)&h_Xb, g_Xb);
    cudaGetSymbolAddress((void**)&h_edge, g_edge);
    cudaGetSymbolAddress((void**)&h_Wh, g_Wh);

    k_xh<<<4096, 256>>>((const float4*)x0, (const float4*)x1, (const float4*)x2,
                        (const float4*)x3, (const float4*)x4);
    k_prep<<<6329, 256>>>(rows, cols, vals);
    k_wconv<<<720, 256>>>(Whmc);

    const int AGG_BLOCKS = TOTAL_S / 40;   // 20250
    // L0: Xh(inputs) -> Xh only
    k_agg<<<AGG_BLOCKS, 256>>>(h_edge);
    k_gemm<<<2425, 256, SMEM_BYTES>>>(h_Wh,           h_Xa, h_Xa, 0, 0, 1);
    // L1: Xh -> Xb (fp32 residual source) + Xh
    k_agg<<<AGG_BLOCKS, 256>>>(h_edge);
    k_gemm<<<2425, 256, SMEM_BYTES>>>(h_Wh + 15*4096, h_Xa, h_Xb, 0, 1, 1);
    // L2: Xh -> Xa (fp32 pooling), residual from Xb, no fp16 out
    k_agg<<<AGG_BLOCKS, 256>>>(h_edge);
    k_gemm<<<2425, 256, SMEM_BYTES>>>(h_Wh + 30*4096, h_Xb, h_Xa, 1, 1, 0);

    k_pool_init<<<1, 320>>>();
    k_pool<<<dim3(256, 5), 256>>>();
    k_pool_fin<<<6, 256>>>(gf);
    k_fc1<<<16, 256>>>(fc1w, fc1b);
    k_tail<<<1, 128>>>(fc2w, fc2b, fc3w, fc3b, fc4w, fc4b, out);
}

// round 16
// speedup vs baseline: 1.1762x; 1.0674x over previous
#include <cuda_runtime.h>
#include <cuda_fp16.h>
#include <mma.h>
#include <math.h>

using namespace nvcuda;

typedef unsigned long long ull;
typedef unsigned int uint;

// ---------------- problem constants ----------------
#define C 64
#define NTOT 310000
#define TOTAL_E 6480000
#define TOTAL_S 810000

__constant__ int c_EOFF[16] = {0,400000,1200000,2000000,2320000,2480000,3280000,
                               4080000,4400000,4560000,5360000,5680000,5840000,
                               6160000,6320000,6480000};
__constant__ int c_SOFF[16] = {0,50000,150000,250000,290000,310000,410000,510000,
                               550000,570000,670000,710000,730000,770000,790000,810000};
// gw/10000 -> pair index (all SOFF are multiples of 10000)
__constant__ char c_KLUT[81] = {
    0,0,0,0,0,
    1,1,1,1,1,1,1,1,1,1,
    2,2,2,2,2,2,2,2,2,2,
    3,3,3,3,
    4,4,
    5,5,5,5,5,5,5,5,5,5,
    6,6,6,6,6,6,6,6,6,6,
    7,7,7,7,
    8,8,
    9,9,9,9,9,9,9,9,9,9,
    10,10,10,10,
    11,11,
    12,12,12,12,
    13,13,
    14,14};
// source-rank feature offset (rows) per pair
__constant__ int c_XOFFI[15] = {0,50000,150000,250000,290000, 0,0,0,0,
                                50000,50000,50000, 150000,150000, 250000};
// gemm block schedule: heavy ranks first (128 rows/block)
__constant__ int c_GB[6] = {0,157,470,1252,2034,2425};
__constant__ int c_GJ[5] = {4,3,2,1,0};
__constant__ int c_JN[5]  = {50000,100000,100000,40000,20000};
__constant__ int c_JXO[5] = {0,50000,150000,250000,290000};
__constant__ int c_NPJ[5] = {1,2,3,4,5};
__constant__ int c_PAIRK[5][5] = {{0,0,0,0,0},{1,5,0,0,0},{2,6,9,0,0},
                                  {3,7,10,12,0},{4,8,11,13,14}};

// ---------------- device scratch ----------------
__device__ float  g_Xa[(size_t)NTOT*C];    // fp32 features (pooling / L2 out)
__device__ __half g_Xh[(size_t)NTOT*C];    // fp16 gather mirror + residual source
__device__ __half g_Sh[(size_t)TOTAL_S*C]; // aggregated messages fp16 (104MB)
__device__ __half g_Wh[45*4096];           // fp16 weights
__device__ int2   g_edge[TOTAL_E];         // packed (col*128 bytes, half2(v,v))
__device__ int    g_rowptr[TOTAL_S];
__device__ float  g_sum[320];
__device__ float  g_sq[320];
__device__ int    g_mx[320];
__device__ int    g_mn[320];
__device__ float  g_h1[512];

// ---------------- helpers ----------------
__device__ __forceinline__ int fenc(float f) {
    int i = __float_as_int(f);
    return i >= 0 ? i : (i ^ 0x7fffffff);
}
__device__ __forceinline__ float fdec(int i) {
    return __int_as_float(i >= 0 ? i : (i ^ 0x7fffffff));
}
__device__ __forceinline__ __half2 h2zero() {
    return __half2half2(__ushort_as_half((unsigned short)0));
}
__device__ __forceinline__ void hfma_e(int vbits, uint hv, __half2& a) {
    a = __hfma2(*(__half2*)&vbits, *(__half2*)&hv, a);
}

// ---------------- fused prep: pack edges + rowptr ---------------------------
// edge.x = col*128 (byte offset of the source row), edge.y = half2(val,val)
__device__ __forceinline__ int val2h2(float v) {
    __half2 h = __half2half2(__float2half(v));
    return *(int*)&h;
}
__global__ void k_prep(const int* __restrict__ rows, const int* __restrict__ cols,
                       const float* __restrict__ vals) {
    int t = blockIdx.x * blockDim.x + threadIdx.x;
    int e0 = t * 4;
    if (e0 >= TOTAL_E) return;

    int4 c4 = *(const int4*)(cols + e0);
    float4 v4 = *(const float4*)(vals + e0);
    int4 p0 = make_int4(c4.x << 7, val2h2(v4.x), c4.y << 7, val2h2(v4.y));
    int4 p1 = make_int4(c4.z << 7, val2h2(v4.z), c4.w << 7, val2h2(v4.w));
    *(int4*)(g_edge + e0)     = p0;
    *(int4*)(g_edge + e0 + 2) = p1;

    // rowptr mark
    int k = 0;
    while (e0 >= c_EOFF[k + 1]) ++k;
    int le0 = e0 - c_EOFF[k];
    int Ek = c_EOFF[k + 1] - c_EOFF[k];
    int Nj = c_SOFF[k + 1] - c_SOFF[k];
    int4 r4 = *(const int4*)(rows + e0);
    int prev = (le0 > 0) ? __ldg(rows + e0 - 1) : -1;
    int* w = g_rowptr + c_SOFF[k];
    int rr[4] = {r4.x, r4.y, r4.z, r4.w};
    #pragma unroll
    for (int q = 0; q < 4; ++q) {
        int r = rr[q];
        if (r > prev)
            for (int x = prev + 1; x <= r; ++x) w[x] = le0 + q;
        prev = r;
    }
    if (le0 + 4 >= Ek)
        for (int x = prev + 1; x < Nj; ++x) w[x] = Ek;
}

__global__ void k_wconv(const float* __restrict__ W) {
    int i = blockIdx.x * blockDim.x + threadIdx.x;
    if (i < 45 * 4096) g_Wh[i] = __float2half(__ldg(W + i));
}
// concat inputs -> g_Xh (fp16)
__global__ void k_xh(const float4* __restrict__ x0, const float4* __restrict__ x1,
                     const float4* __restrict__ x2, const float4* __restrict__ x3,
                     const float4* __restrict__ x4) {
    const int B1 = 800000, B2 = 2400000, B3 = 4000000, B4 = 4640000, B5 = 4960000;
    uint2* Xh = (uint2*)g_Xh;
    for (int i = blockIdx.x * blockDim.x + threadIdx.x; i < B5;
         i += gridDim.x * blockDim.x) {
        float4 v;
        if      (i < B1) v = __ldg(x0 + i);
        else if (i < B2) v = __ldg(x1 + (i - B1));
        else if (i < B3) v = __ldg(x2 + (i - B2));
        else if (i < B4) v = __ldg(x3 + (i - B3));
        else             v = __ldg(x4 + (i - B4));
        __half2 h0 = __floats2half2_rn(v.x, v.y);
        __half2 h1 = __floats2half2_rn(v.z, v.w);
        uint2 u;
        u.x = *(uint*)&h0; u.y = *(uint*)&h1;
        Xh[i] = u;
    }
}

// ---------------- sparse aggregation: smem edge + rowptr staging ------------
// block = 40 rows of one pair. Phase 1 bulk-loads the edge span + rowptr
// bounds into smem. Phase 2: 8 warps x 5 rows; edges via LDS, HFMA2 accum.
#define ECAP 1536
__global__ void __launch_bounds__(256)
k_agg(const int2* __restrict__ edge) {
    __shared__ int2 sE[ECAP];
    __shared__ int  sRP[41];
    int b = blockIdx.x;
    int gw0 = b * 40;
    int k = c_KLUT[gw0 / 10000];
    int r0 = gw0 - c_SOFF[k];
    int Nj = c_SOFF[k + 1] - c_SOFF[k];
    int Ek = c_EOFF[k + 1] - c_EOFF[k];

    const int*  rp    = g_rowptr + c_SOFF[k];
    const int2* pedge = edge + c_EOFF[k];
    const char* srcb  = (const char*)(g_Xh + (size_t)c_XOFFI[k] * C);

    if (threadIdx.x <= 40) {
        int rr = r0 + threadIdx.x;
        sRP[threadIdx.x] = (rr < Nj) ? __ldg(rp + rr) : Ek;
    }
    __syncthreads();
    int base = sRP[0];
    int ncap = min(sRP[40] - base, ECAP);
    for (int i = threadIdx.x; i < ncap; i += 256)
        sE[i] = __ldcs(pedge + base + i);
    __syncthreads();

    int warp = threadIdx.x >> 5;
    int lane = threadIdx.x & 31;
    int laneB = lane * 4;
    int r = r0 + warp * 5;

    int bs[6];
    #pragma unroll
    for (int i = 0; i < 6; ++i) bs[i] = sRP[warp * 5 + i];

    __half* Sout = g_Sh + (size_t)(c_SOFF[k] + r) * C + lane * 2;
    #pragma unroll
    for (int q = 0; q < 5; ++q) {
        int es = bs[q], ee = bs[q + 1];
        __half2 a0 = h2zero(), a1 = h2zero();
        if (ee - base <= ncap) {
            int e = es - base, eend = ee - base;
            if ((e & 1) && e < eend) {
                int2 ed = sE[e];
                uint hv = *(const uint*)(srcb + (size_t)(unsigned)ed.x + laneB);
                hfma_e(ed.y, hv, a0);
                ++e;
            }
            while (e + 4 <= eend) {
                int4 ea = *(const int4*)(sE + e);
                int4 eb = *(const int4*)(sE + e + 2);
                uint h0 = *(const uint*)(srcb + (size_t)(unsigned)ea.x + laneB);
                uint h1 = *(const uint*)(srcb + (size_t)(unsigned)ea.z + laneB);
                uint h2 = *(const uint*)(srcb + (size_t)(unsigned)eb.x + laneB);
                uint h3 = *(const uint*)(srcb + (size_t)(unsigned)eb.z + laneB);
                hfma_e(ea.y, h0, a0); hfma_e(ea.w, h1, a1);
                hfma_e(eb.y, h2, a0); hfma_e(eb.w, h3, a1);
                e += 4;
            }
            if (e + 2 <= eend) {
                int4 ea = *(const int4*)(sE + e);
                uint h0 = *(const uint*)(srcb + (size_t)(unsigned)ea.x + laneB);
                uint h1 = *(const uint*)(srcb + (size_t)(unsigned)ea.z + laneB);
                hfma_e(ea.y, h0, a0); hfma_e(ea.w, h1, a1);
                e += 2;
            }
            if (e < eend) {
                int2 ed = sE[e];
                uint hv = *(const uint*)(srcb + (size_t)(unsigned)ed.x + laneB);
                hfma_e(ed.y, hv, a0);
            }
        } else {
            for (int e = es; e < ee; ++e) {
                int2 ed = __ldcs(pedge + e);
                uint hv = *(const uint*)(srcb + (size_t)(unsigned)ed.x + laneB);
                hfma_e(ed.y, hv, a0);
            }
        }
        float2 f0 = __half22float2(a0);
        float2 f1 = __half22float2(a1);
        __half2 h = __floats2half2_rn(f0.x + f1.x, f0.y + f1.y);
        __stcs((uint*)Sout, *(uint*)&h);
        Sout += C;
    }
}

// ---------------- tensor-core GEMM + residual + relu ------------------------
// residual (if any) read from fp16 g_Xh. software-pipelined S/W tile loads.
#define SS_LD 72
#define SO_LD 68
__global__ void __launch_bounds__(256)
k_gemm(const __half* __restrict__ Whl, float* __restrict__ dstX,
       int resid, int wF32, int wF16) {
    extern __shared__ char smraw[];
    __half* sS = (__half*)smraw;                       // 128 x 72 half
    __half* sW = (__half*)(smraw + 128 * SS_LD * 2);   // 64 x 72 half
    float*  sO = (float*)smraw;                        // epilogue: 128 x 68 f32

    int b = blockIdx.x;
    int ji = 0;
    while (b >= c_GB[ji + 1]) ++ji;
    int j = c_GJ[ji];
    int rowBase = (b - c_GB[ji]) * 128;
    int Nj = c_JN[j];

    int tid  = threadIdx.x;
    int warp = tid >> 5;

    int sr[8], sc[8], wr[4], wc[4];
    #pragma unroll
    for (int i = 0; i < 8; ++i) {
        int t = tid + i * 256;
        sr[i] = t >> 4; sc[i] = (t & 15) * 4;
    }
    #pragma unroll
    for (int i = 0; i < 4; ++i) {
        int t = tid + i * 256;
        wr[i] = t >> 4; wc[i] = (t & 15) * 4;
    }

    wmma::fragment<wmma::accumulator, 16, 16, 16, float> acc[4];
    #pragma unroll
    for (int n = 0; n < 4; ++n) wmma::fill_fragment(acc[n], 0.f);

    int np = c_NPJ[j];
    uint2 sreg[8], wreg[4];

    {
        int k = c_PAIRK[j][0];
        const __half* W = Whl + k * 4096;
        const __half* S = g_Sh + (size_t)(c_SOFF[k] + rowBase) * C;
        #pragma unroll
        for (int i = 0; i < 8; ++i) {
            sreg[i] = make_uint2(0, 0);
            if (rowBase + sr[i] < Nj)
                sreg[i] = __ldcs((const uint2*)(S + (size_t)sr[i] * C + sc[i]));
        }
        #pragma unroll
        for (int i = 0; i < 4; ++i)
            wreg[i] = *(const uint2*)(W + wr[i] * C + wc[i]);
    }

    for (int p = 0; p < np; ++p) {
        #pragma unroll
        for (int i = 0; i < 8; ++i)
            *(uint2*)(sS + sr[i] * SS_LD + sc[i]) = sreg[i];
        #pragma unroll
        for (int i = 0; i < 4; ++i)
            *(uint2*)(sW + wr[i] * SS_LD + wc[i]) = wreg[i];
        __syncthreads();

        if (p + 1 < np) {
            int k = c_PAIRK[j][p + 1];
            const __half* W = Whl + k * 4096;
            const __half* S = g_Sh + (size_t)(c_SOFF[k] + rowBase) * C;
            #pragma unroll
            for (int i = 0; i < 8; ++i) {
                sreg[i] = make_uint2(0, 0);
                if (rowBase + sr[i] < Nj)
                    sreg[i] = __ldcs((const uint2*)(S + (size_t)sr[i] * C + sc[i]));
            }
            #pragma unroll
            for (int i = 0; i < 4; ++i)
                wreg[i] = *(const uint2*)(W + wr[i] * C + wc[i]);
        }

        #pragma unroll
        for (int k0 = 0; k0 < 64; k0 += 16) {
            wmma::fragment<wmma::matrix_a, 16, 16, 16, __half, wmma::row_major> af;
            wmma::load_matrix_sync(af, sS + warp * 16 * SS_LD + k0, SS_LD);
            #pragma unroll
            for (int n = 0; n < 4; ++n) {
                wmma::fragment<wmma::matrix_b, 16, 16, 16, __half, wmma::row_major> bf;
                wmma::load_matrix_sync(bf, sW + k0 * SS_LD + n * 16, SS_LD);
                wmma::mma_sync(acc[n], af, bf, acc[n]);
            }
        }
        __syncthreads();
    }

    #pragma unroll
    for (int n = 0; n < 4; ++n)
        wmma::store_matrix_sync(sO + warp * 16 * SO_LD + n * 16, acc[n], SO_LD,
                                wmma::mem_row_major);
    __syncthreads();

    float* Xd = dstX + (size_t)c_JXO[j] * C;
    __half* Xh = g_Xh + (size_t)c_JXO[j] * C;
    #pragma unroll
    for (int t = tid; t < 2048; t += 256) {
        int r = t >> 4, c4 = (t & 15) * 4;
        int gr = rowBase + r;
        if (gr < Nj) {
            float4 o = *(const float4*)(sO + r * SO_LD + c4);
            if (resid) {
                uint2 u = *(const uint2*)(Xh + (size_t)gr * C + c4);
                float2 xa = __half22float2(*(__half2*)&u.x);
                float2 xb = __half22float2(*(__half2*)&u.y);
                o.x += xa.x; o.y += xa.y; o.z += xb.x; o.w += xb.y;
            }
            o.x = fmaxf(o.x, 0.f); o.y = fmaxf(o.y, 0.f);
            o.z = fmaxf(o.z, 0.f); o.w = fmaxf(o.w, 0.f);
            if (wF32)
                __stcs((float4*)(Xd + (size_t)gr * C + c4), o);
            if (wF16) {
                __half2 h0 = __floats2half2_rn(o.x, o.y);
                __half2 h1 = __floats2half2_rn(o.z, o.w);
                uint2 u;
                u.x = *(uint*)&h0; u.y = *(uint*)&h1;
                *(uint2*)(Xh + (size_t)gr * C + c4) = u;
            }
        }
    }
}

// ---------------- pooling (reads g_Xa) ----------------
__global__ void k_pool_init() {
    int t = threadIdx.x;
    if (t < 320) {
        g_sum[t] = 0.f; g_sq[t] = 0.f;
        g_mx[t] = 0x80000000; g_mn[t] = 0x7fffffff;
    }
}
__global__ void k_pool() {
    int rank = blockIdx.y;
    int c = threadIdx.x & 63;
    int rg = threadIdx.x >> 6;
    int Nr = c_JN[rank];
    const float* base = g_Xa + (size_t)c_JXO[rank] * C;
    float s = 0.f, sq = 0.f, mx = -3.402823466e38f, mn = 3.402823466e38f;
    for (int r = blockIdx.x * 4 + rg; r < Nr; r += gridDim.x * 4) {
        float v = base[(size_t)r * C + c];
        s += v; sq = fmaf(v, v, sq);
        mx = fmaxf(mx, v); mn = fminf(mn, v);
    }
    int o = rank * 64 + c;
    atomicAdd(&g_sum[o], s);
    atomicAdd(&g_sq[o], sq);
    atomicMax(&g_mx[o], fenc(mx));
    atomicMin(&g_mn[o], fenc(mn));
}

// ---------------- MLP head (fc1 recomputes pooled from stats) ---------------
__device__ __forceinline__ float pooled_val(int idx, const float* gf) {
    if (idx >= 1280) return gf[idx - 1280];
    int rank = idx >> 8;
    int part = (idx >> 6) & 3;
    int c = idx & 63;
    int o = rank * 64 + c;
    float Nr = (float)c_JN[rank];
    if (part == 0) return g_sum[o] / Nr;
    if (part == 1) {
        float m = g_sum[o] / Nr;
        float var = g_sq[o] / Nr - m * m;
        var = fmaxf(var, 0.f);
        if (var == 0.f) var = 1e-6f;
        return sqrtf(var);
    }
    if (part == 2) return fdec(g_mx[o]);
    return fdec(g_mn[o]);
}
__global__ void k_fc1(const float* __restrict__ w, const float* __restrict__ b,
                      const float* __restrict__ gf) {
    __shared__ float p[1284];
    __shared__ float red[256];
    for (int i = threadIdx.x; i < 1284; i += 256) p[i] = pooled_val(i, gf);
    __syncthreads();
    int lane = threadIdx.x & 31;
    int rp = threadIdx.x >> 5;
    int o = blockIdx.x * 32 + lane;
    float s = 0.f;
    for (int i = rp; i < 1284; i += 8) s = fmaf(p[i], w[(size_t)i * 512 + o], s);
    red[threadIdx.x] = s;
    __syncthreads();
    if (rp == 0) {
        float t = s;
        #pragma unroll
        for (int q = 1; q < 8; ++q) t += red[q * 32 + lane];
        t += b[o];
        g_h1[o] = fmaxf(t, 0.f);
    }
}
__global__ void k_tail(const float* __restrict__ w2, const float* __restrict__ b2,
                       const float* __restrict__ w3, const float* __restrict__ b3,
                       const float* __restrict__ w4, const float* __restrict__ b4,
                       float* __restrict__ out) {
    __shared__ float h2[128];
    __shared__ float h3[64];
    int tid = threadIdx.x;
    {
        float s = b2[tid];
        for (int i = 0; i < 512; ++i) s = fmaf(g_h1[i], w2[(size_t)i * 128 + tid], s);
        h2[tid] = fmaxf(s, 0.f);
    }
    __syncthreads();
    if (tid < 64) {
        float s = b3[tid];
        for (int i = 0; i < 128; ++i) s = fmaf(h2[i], w3[(size_t)i * 64 + tid], s);
        h3[tid] = fmaxf(s, 0.f);
    }
    __syncthreads();
    if (tid < 2) {
        float s = b4[tid];
        for (int i = 0; i < 64; ++i) s = fmaf(h3[i], w4[(size_t)i * 2 + tid], s);
        out[tid] = (tid == 0) ? s : s * s;
    }
}

// ---------------- host launcher ----------------
extern "C" void kernel_launch(void* const* d_in, const int* in_sizes, int n_in,
                              void* d_out, int out_size) {
    const float* x0 = (const float*)d_in[0];
    const float* x1 = (const float*)d_in[1];
    const float* x2 = (const float*)d_in[2];
    const float* x3 = (const float*)d_in[3];
    const float* x4 = (const float*)d_in[4];
    const int*   rows = (const int*)d_in[5];
    const int*   cols = (const int*)d_in[6];
    const float* vals = (const float*)d_in[7];
    const float* gf   = (const float*)d_in[8];
    const float* Whmc = (const float*)d_in[9];
    const float* fc1w = (const float*)d_in[10];
    const float* fc1b = (const float*)d_in[11];
    const float* fc2w = (const float*)d_in[12];
    const float* fc2b = (const float*)d_in[13];
    const float* fc3w = (const float*)d_in[14];
    const float* fc3b = (const float*)d_in[15];
    const float* fc4w = (const float*)d_in[16];
    const float* fc4b = (const float*)d_in[17];
    float* out = (float*)d_out;

    const int SMEM_BYTES = 34816;
    cudaFuncSetAttribute(k_gemm, cudaFuncAttributeMaxDynamicSharedMemorySize,
                         SMEM_BYTES);

    float* h_Xa = nullptr;
    int2* h_edge = nullptr;
    __half* h_Wh = nullptr;
    cudaGetSymbolAddress((void**)&h_Xa, g_Xa);
    cudaGetSymbolAddress((void**)&h_edge, g_edge);
    cudaGetSymbolAddress((void**)&h_Wh, g_Wh);

    k_xh<<<4096, 256>>>((const float4*)x0, (const float4*)x1, (const float4*)x2,
                        (const float4*)x3, (const float4*)x4);
    k_prep<<<6329, 256>>>(rows, cols, vals);
    k_wconv<<<720, 256>>>(Whmc);

    const int AGG_BLOCKS = TOTAL_S / 40;   // 20250
    // L0: Xh(inputs) -> Xh only
    k_agg<<<AGG_BLOCKS, 256>>>(h_edge);
    k_gemm<<<2425, 256, SMEM_BYTES>>>(h_Wh,           h_Xa, 0, 0, 1);
    // L1: Xh -> Xh only (residual source for L2 is this fp16 output)
    k_agg<<<AGG_BLOCKS, 256>>>(h_edge);
    k_gemm<<<2425, 256, SMEM_BYTES>>>(h_Wh + 15*4096, h_Xa, 0, 0, 1);
    // L2: Xh -> Xa (fp32 pooling), residual from Xh (fp16), no fp16 out
    k_agg<<<AGG_BLOCKS, 256>>>(h_edge);
    k_gemm<<<2425, 256, SMEM_BYTES>>>(h_Wh + 30*4096, h_Xa, 1, 1, 0);

    k_pool_init<<<1, 320>>>();
    k_pool<<<dim3(256, 5), 256>>>();
    k_fc1<<<16, 256>>>(fc1w, fc1b, gf);
    k_tail<<<1, 128>>>(fc2w, fc2b, fc3w, fc3b, fc4w, fc4b, out);
}

// round 17
// speedup vs baseline: 1.2487x; 1.0616x over previous
#include <cuda_runtime.h>
#include <cuda_fp16.h>
#include <mma.h>
#include <math.h>

using namespace nvcuda;

typedef unsigned long long ull;
typedef unsigned int uint;

// ---------------- problem constants ----------------
#define C 64
#define NTOT 310000
#define TOTAL_E 6480000
#define TOTAL_S 810000

__constant__ int c_EOFF[16] = {0,400000,1200000,2000000,2320000,2480000,3280000,
                               4080000,4400000,4560000,5360000,5680000,5840000,
                               6160000,6320000,6480000};
__constant__ int c_SOFF[16] = {0,50000,150000,250000,290000,310000,410000,510000,
                               550000,570000,670000,710000,730000,770000,790000,810000};
// gw/10000 -> pair index (all SOFF are multiples of 10000)
__constant__ char c_KLUT[81] = {
    0,0,0,0,0,
    1,1,1,1,1,1,1,1,1,1,
    2,2,2,2,2,2,2,2,2,2,
    3,3,3,3,
    4,4,
    5,5,5,5,5,5,5,5,5,5,
    6,6,6,6,6,6,6,6,6,6,
    7,7,7,7,
    8,8,
    9,9,9,9,9,9,9,9,9,9,
    10,10,10,10,
    11,11,
    12,12,12,12,
    13,13,
    14,14};
// source-rank feature offset (rows) per pair
__constant__ int c_XOFFI[15] = {0,50000,150000,250000,290000, 0,0,0,0,
                                50000,50000,50000, 150000,150000, 250000};
// gemm block schedule: heavy ranks first (128 rows/block)
__constant__ int c_GB[6] = {0,157,470,1252,2034,2425};
__constant__ int c_GJ[5] = {4,3,2,1,0};
__constant__ int c_JN[5]  = {50000,100000,100000,40000,20000};
__constant__ int c_JXO[5] = {0,50000,150000,250000,290000};
__constant__ int c_NPJ[5] = {1,2,3,4,5};
__constant__ int c_PAIRK[5][5] = {{0,0,0,0,0},{1,5,0,0,0},{2,6,9,0,0},
                                  {3,7,10,12,0},{4,8,11,13,14}};

// ---------------- device scratch ----------------
__device__ __half g_Xh[(size_t)NTOT*C];    // fp16 features (gather + residual)
__device__ __half g_Sh[(size_t)TOTAL_S*C]; // aggregated messages fp16 (104MB)
__device__ __half g_Wh[45*4096];           // fp16 weights
__device__ int2   g_edge[TOTAL_E];         // packed (col*128 bytes, half2(v,v))
__device__ int    g_rowptr[TOTAL_S];
__device__ float  g_sum[320];
__device__ float  g_sq[320];
__device__ int    g_mx[320];
__device__ int    g_mn[320];
__device__ float  g_h1[512];

// ---------------- helpers ----------------
__device__ __forceinline__ int fenc(float f) {
    int i = __float_as_int(f);
    return i >= 0 ? i : (i ^ 0x7fffffff);
}
__device__ __forceinline__ float fdec(int i) {
    return __int_as_float(i >= 0 ? i : (i ^ 0x7fffffff));
}
__device__ __forceinline__ __half2 h2zero() {
    return __half2half2(__ushort_as_half((unsigned short)0));
}
__device__ __forceinline__ void hfma_e(int vbits, uint hv, __half2& a) {
    a = __hfma2(*(__half2*)&vbits, *(__half2*)&hv, a);
}

// ---------------- fused prep: pack edges + rowptr ---------------------------
__device__ __forceinline__ int val2h2(float v) {
    __half2 h = __half2half2(__float2half(v));
    return *(int*)&h;
}
__global__ void k_prep(const int* __restrict__ rows, const int* __restrict__ cols,
                       const float* __restrict__ vals) {
    int t = blockIdx.x * blockDim.x + threadIdx.x;
    int e0 = t * 4;
    if (e0 >= TOTAL_E) return;

    int4 c4 = *(const int4*)(cols + e0);
    float4 v4 = *(const float4*)(vals + e0);
    int4 p0 = make_int4(c4.x << 7, val2h2(v4.x), c4.y << 7, val2h2(v4.y));
    int4 p1 = make_int4(c4.z << 7, val2h2(v4.z), c4.w << 7, val2h2(v4.w));
    *(int4*)(g_edge + e0)     = p0;
    *(int4*)(g_edge + e0 + 2) = p1;

    int k = 0;
    while (e0 >= c_EOFF[k + 1]) ++k;
    int le0 = e0 - c_EOFF[k];
    int Ek = c_EOFF[k + 1] - c_EOFF[k];
    int Nj = c_SOFF[k + 1] - c_SOFF[k];
    int4 r4 = *(const int4*)(rows + e0);
    int prev = (le0 > 0) ? __ldg(rows + e0 - 1) : -1;
    int* w = g_rowptr + c_SOFF[k];
    int rr[4] = {r4.x, r4.y, r4.z, r4.w};
    #pragma unroll
    for (int q = 0; q < 4; ++q) {
        int r = rr[q];
        if (r > prev)
            for (int x = prev + 1; x <= r; ++x) w[x] = le0 + q;
        prev = r;
    }
    if (le0 + 4 >= Ek)
        for (int x = prev + 1; x < Nj; ++x) w[x] = Ek;
}

__global__ void k_wconv(const float* __restrict__ W) {
    int i = blockIdx.x * blockDim.x + threadIdx.x;
    if (i < 45 * 4096) g_Wh[i] = __float2half(__ldg(W + i));
}
// concat inputs -> g_Xh (fp16)
__global__ void k_xh(const float4* __restrict__ x0, const float4* __restrict__ x1,
                     const float4* __restrict__ x2, const float4* __restrict__ x3,
                     const float4* __restrict__ x4) {
    const int B1 = 800000, B2 = 2400000, B3 = 4000000, B4 = 4640000, B5 = 4960000;
    uint2* Xh = (uint2*)g_Xh;
    for (int i = blockIdx.x * blockDim.x + threadIdx.x; i < B5;
         i += gridDim.x * blockDim.x) {
        float4 v;
        if      (i < B1) v = __ldg(x0 + i);
        else if (i < B2) v = __ldg(x1 + (i - B1));
        else if (i < B3) v = __ldg(x2 + (i - B2));
        else if (i < B4) v = __ldg(x3 + (i - B3));
        else             v = __ldg(x4 + (i - B4));
        __half2 h0 = __floats2half2_rn(v.x, v.y);
        __half2 h1 = __floats2half2_rn(v.z, v.w);
        uint2 u;
        u.x = *(uint*)&h0; u.y = *(uint*)&h1;
        Xh[i] = u;
    }
}

// ---------------- sparse aggregation: smem edge + rowptr staging ------------
#define ECAP 1536
__global__ void __launch_bounds__(256, 6)
k_agg(const int2* __restrict__ edge) {
    __shared__ int2 sE[ECAP];
    __shared__ int  sRP[41];
    int b = blockIdx.x;
    int gw0 = b * 40;
    int k = c_KLUT[gw0 / 10000];
    int r0 = gw0 - c_SOFF[k];
    int Nj = c_SOFF[k + 1] - c_SOFF[k];
    int Ek = c_EOFF[k + 1] - c_EOFF[k];

    const int*  rp    = g_rowptr + c_SOFF[k];
    const int2* pedge = edge + c_EOFF[k];
    const char* srcb  = (const char*)(g_Xh + (size_t)c_XOFFI[k] * C);

    if (threadIdx.x <= 40) {
        int rr = r0 + threadIdx.x;
        sRP[threadIdx.x] = (rr < Nj) ? __ldg(rp + rr) : Ek;
    }
    __syncthreads();
    int base = sRP[0];
    int ncap = min(sRP[40] - base, ECAP);
    for (int i = threadIdx.x; i < ncap; i += 256)
        sE[i] = __ldcs(pedge + base + i);
    __syncthreads();

    int warp = threadIdx.x >> 5;
    int lane = threadIdx.x & 31;
    int laneB = lane * 4;
    int r = r0 + warp * 5;

    int bs[6];
    #pragma unroll
    for (int i = 0; i < 6; ++i) bs[i] = sRP[warp * 5 + i];

    __half* Sout = g_Sh + (size_t)(c_SOFF[k] + r) * C + lane * 2;
    #pragma unroll
    for (int q = 0; q < 5; ++q) {
        int es = bs[q], ee = bs[q + 1];
        __half2 a0 = h2zero(), a1 = h2zero();
        if (ee - base <= ncap) {
            int e = es - base, eend = ee - base;
            if ((e & 1) && e < eend) {
                int2 ed = sE[e];
                uint hv = *(const uint*)(srcb + (size_t)(unsigned)ed.x + laneB);
                hfma_e(ed.y, hv, a0);
                ++e;
            }
            while (e + 4 <= eend) {
                int4 ea = *(const int4*)(sE + e);
                int4 eb = *(const int4*)(sE + e + 2);
                uint h0 = *(const uint*)(srcb + (size_t)(unsigned)ea.x + laneB);
                uint h1 = *(const uint*)(srcb + (size_t)(unsigned)ea.z + laneB);
                uint h2 = *(const uint*)(srcb + (size_t)(unsigned)eb.x + laneB);
                uint h3 = *(const uint*)(srcb + (size_t)(unsigned)eb.z + laneB);
                hfma_e(ea.y, h0, a0); hfma_e(ea.w, h1, a1);
                hfma_e(eb.y, h2, a0); hfma_e(eb.w, h3, a1);
                e += 4;
            }
            if (e + 2 <= eend) {
                int4 ea = *(const int4*)(sE + e);
                uint h0 = *(const uint*)(srcb + (size_t)(unsigned)ea.x + laneB);
                uint h1 = *(const uint*)(srcb + (size_t)(unsigned)ea.z + laneB);
                hfma_e(ea.y, h0, a0); hfma_e(ea.w, h1, a1);
                e += 2;
            }
            if (e < eend) {
                int2 ed = sE[e];
                uint hv = *(const uint*)(srcb + (size_t)(unsigned)ed.x + laneB);
                hfma_e(ed.y, hv, a0);
            }
        } else {
            for (int e = es; e < ee; ++e) {
                int2 ed = __ldcs(pedge + e);
                uint hv = *(const uint*)(srcb + (size_t)(unsigned)ed.x + laneB);
                hfma_e(ed.y, hv, a0);
            }
        }
        float2 f0 = __half22float2(a0);
        float2 f1 = __half22float2(a1);
        __half2 h = __floats2half2_rn(f0.x + f1.x, f0.y + f1.y);
        __stcs((uint*)Sout, *(uint*)&h);
        Sout += C;
    }
}

// ---------------- tensor-core GEMM + residual + relu (+fused pooling) -------
// residual from fp16 g_Xh. doPool: block-reduce per-column stats + atomics.
#define SS_LD 72
#define SO_LD 68
__global__ void __launch_bounds__(256)
k_gemm(const __half* __restrict__ Whl, int resid, int doPool, int wF16) {
    extern __shared__ char smraw[];
    __half* sS = (__half*)smraw;                       // 128 x 72 half
    __half* sW = (__half*)(smraw + 128 * SS_LD * 2);   // 64 x 72 half
    float*  sO = (float*)smraw;                        // epilogue: 128 x 68 f32

    int b = blockIdx.x;
    int ji = 0;
    while (b >= c_GB[ji + 1]) ++ji;
    int j = c_GJ[ji];
    int rowBase = (b - c_GB[ji]) * 128;
    int Nj = c_JN[j];

    int tid  = threadIdx.x;
    int warp = tid >> 5;

    int sr[8], sc[8], wr[4], wc[4];
    #pragma unroll
    for (int i = 0; i < 8; ++i) {
        int t = tid + i * 256;
        sr[i] = t >> 4; sc[i] = (t & 15) * 4;
    }
    #pragma unroll
    for (int i = 0; i < 4; ++i) {
        int t = tid + i * 256;
        wr[i] = t >> 4; wc[i] = (t & 15) * 4;
    }

    wmma::fragment<wmma::accumulator, 16, 16, 16, float> acc[4];
    #pragma unroll
    for (int n = 0; n < 4; ++n) wmma::fill_fragment(acc[n], 0.f);

    int np = c_NPJ[j];
    uint2 sreg[8], wreg[4];

    {
        int k = c_PAIRK[j][0];
        const __half* W = Whl + k * 4096;
        const __half* S = g_Sh + (size_t)(c_SOFF[k] + rowBase) * C;
        #pragma unroll
        for (int i = 0; i < 8; ++i) {
            sreg[i] = make_uint2(0, 0);
            if (rowBase + sr[i] < Nj)
                sreg[i] = __ldcs((const uint2*)(S + (size_t)sr[i] * C + sc[i]));
        }
        #pragma unroll
        for (int i = 0; i < 4; ++i)
            wreg[i] = *(const uint2*)(W + wr[i] * C + wc[i]);
    }

    for (int p = 0; p < np; ++p) {
        #pragma unroll
        for (int i = 0; i < 8; ++i)
            *(uint2*)(sS + sr[i] * SS_LD + sc[i]) = sreg[i];
        #pragma unroll
        for (int i = 0; i < 4; ++i)
            *(uint2*)(sW + wr[i] * SS_LD + wc[i]) = wreg[i];
        __syncthreads();

        if (p + 1 < np) {
            int k = c_PAIRK[j][p + 1];
            const __half* W = Whl + k * 4096;
            const __half* S = g_Sh + (size_t)(c_SOFF[k] + rowBase) * C;
            #pragma unroll
            for (int i = 0; i < 8; ++i) {
                sreg[i] = make_uint2(0, 0);
                if (rowBase + sr[i] < Nj)
                    sreg[i] = __ldcs((const uint2*)(S + (size_t)sr[i] * C + sc[i]));
            }
            #pragma unroll
            for (int i = 0; i < 4; ++i)
                wreg[i] = *(const uint2*)(W + wr[i] * C + wc[i]);
        }

        #pragma unroll
        for (int k0 = 0; k0 < 64; k0 += 16) {
            wmma::fragment<wmma::matrix_a, 16, 16, 16, __half, wmma::row_major> af;
            wmma::load_matrix_sync(af, sS + warp * 16 * SS_LD + k0, SS_LD);
            #pragma unroll
            for (int n = 0; n < 4; ++n) {
                wmma::fragment<wmma::matrix_b, 16, 16, 16, __half, wmma::row_major> bf;
                wmma::load_matrix_sync(bf, sW + k0 * SS_LD + n * 16, SS_LD);
                wmma::mma_sync(acc[n], af, bf, acc[n]);
            }
        }
        __syncthreads();
    }

    #pragma unroll
    for (int n = 0; n < 4; ++n)
        wmma::store_matrix_sync(sO + warp * 16 * SO_LD + n * 16, acc[n], SO_LD,
                                wmma::mem_row_major);
    __syncthreads();

    __half* Xh = g_Xh + (size_t)c_JXO[j] * C;
    float ps[4] = {0.f, 0.f, 0.f, 0.f};
    float pq[4] = {0.f, 0.f, 0.f, 0.f};
    float pmx[4] = {-3.402823466e38f, -3.402823466e38f,
                    -3.402823466e38f, -3.402823466e38f};
    float pmn[4] = {3.402823466e38f, 3.402823466e38f,
                    3.402823466e38f, 3.402823466e38f};

    #pragma unroll
    for (int t = tid; t < 2048; t += 256) {
        int r = t >> 4, c4 = (t & 15) * 4;
        int gr = rowBase + r;
        if (gr < Nj) {
            float4 o = *(const float4*)(sO + r * SO_LD + c4);
            if (resid) {
                uint2 u = *(const uint2*)(Xh + (size_t)gr * C + c4);
                float2 xa = __half22float2(*(__half2*)&u.x);
                float2 xb = __half22float2(*(__half2*)&u.y);
                o.x += xa.x; o.y += xa.y; o.z += xb.x; o.w += xb.y;
            }
            o.x = fmaxf(o.x, 0.f); o.y = fmaxf(o.y, 0.f);
            o.z = fmaxf(o.z, 0.f); o.w = fmaxf(o.w, 0.f);
            if (wF16) {
                __half2 h0 = __floats2half2_rn(o.x, o.y);
                __half2 h1 = __floats2half2_rn(o.z, o.w);
                uint2 u;
                u.x = *(uint*)&h0; u.y = *(uint*)&h1;
                *(uint2*)(Xh + (size_t)gr * C + c4) = u;
            }
            if (doPool) {
                float oo[4] = {o.x, o.y, o.z, o.w};
                #pragma unroll
                for (int v = 0; v < 4; ++v) {
                    ps[v] += oo[v];
                    pq[v] = fmaf(oo[v], oo[v], pq[v]);
                    pmx[v] = fmaxf(pmx[v], oo[v]);
                    pmn[v] = fminf(pmn[v], oo[v]);
                }
            }
        }
    }

    if (doPool) {
        __syncthreads();
        float* smf = (float*)smraw;     // 256 x 16 partials
        #pragma unroll
        for (int v = 0; v < 4; ++v) {
            smf[tid * 16 + v * 4 + 0] = ps[v];
            smf[tid * 16 + v * 4 + 1] = pq[v];
            smf[tid * 16 + v * 4 + 2] = pmx[v];
            smf[tid * 16 + v * 4 + 3] = pmn[v];
        }
        __syncthreads();
        // 256 work items: col = tid&63, stat = tid>>6. 16 contributors each.
        int col = tid & 63;
        int st  = tid >> 6;
        int g   = col >> 2, c = col & 3;
        float acc0 = smf[g * 16 + c * 4 + st];
        #pragma unroll
        for (int i = 1; i < 16; ++i) {
            float v = smf[(g + 16 * i) * 16 + c * 4 + st];
            if (st == 0 || st == 1) acc0 += v;
            else if (st == 2) acc0 = fmaxf(acc0, v);
            else acc0 = fminf(acc0, v);
        }
        int o = j * 64 + col;
        if (st == 0) atomicAdd(&g_sum[o], acc0);
        else if (st == 1) atomicAdd(&g_sq[o], acc0);
        else if (st == 2) atomicMax(&g_mx[o], fenc(acc0));
        else atomicMin(&g_mn[o], fenc(acc0));
    }
}

// ---------------- pooling init ----------------
__global__ void k_pool_init() {
    int t = threadIdx.x;
    if (t < 320) {
        g_sum[t] = 0.f; g_sq[t] = 0.f;
        g_mx[t] = 0x80000000; g_mn[t] = 0x7fffffff;
    }
}

// ---------------- MLP head (fc1 recomputes pooled from stats) ---------------
__device__ __forceinline__ float pooled_val(int idx, const float* gf) {
    if (idx >= 1280) return gf[idx - 1280];
    int rank = idx >> 8;
    int part = (idx >> 6) & 3;
    int c = idx & 63;
    int o = rank * 64 + c;
    float Nr = (float)c_JN[rank];
    if (part == 0) return g_sum[o] / Nr;
    if (part == 1) {
        float m = g_sum[o] / Nr;
        float var = g_sq[o] / Nr - m * m;
        var = fmaxf(var, 0.f);
        if (var == 0.f) var = 1e-6f;
        return sqrtf(var);
    }
    if (part == 2) return fdec(g_mx[o]);
    return fdec(g_mn[o]);
}
__global__ void k_fc1(const float* __restrict__ w, const float* __restrict__ b,
                      const float* __restrict__ gf) {
    __shared__ float p[1284];
    __shared__ float red[256];
    for (int i = threadIdx.x; i < 1284; i += 256) p[i] = pooled_val(i, gf);
    __syncthreads();
    int lane = threadIdx.x & 31;
    int rp = threadIdx.x >> 5;
    int o = blockIdx.x * 32 + lane;
    float s = 0.f;
    for (int i = rp; i < 1284; i += 8) s = fmaf(p[i], w[(size_t)i * 512 + o], s);
    red[threadIdx.x] = s;
    __syncthreads();
    if (rp == 0) {
        float t = s;
        #pragma unroll
        for (int q = 1; q < 8; ++q) t += red[q * 32 + lane];
        t += b[o];
        g_h1[o] = fmaxf(t, 0.f);
    }
}
__global__ void k_tail(const float* __restrict__ w2, const float* __restrict__ b2,
                       const float* __restrict__ w3, const float* __restrict__ b3,
                       const float* __restrict__ w4, const float* __restrict__ b4,
                       float* __restrict__ out) {
    __shared__ float h2[128];
    __shared__ float h3[64];
    int tid = threadIdx.x;
    {
        float s = b2[tid];
        for (int i = 0; i < 512; ++i) s = fmaf(g_h1[i], w2[(size_t)i * 128 + tid], s);
        h2[tid] = fmaxf(s, 0.f);
    }
    __syncthreads();
    if (tid < 64) {
        float s = b3[tid];
        for (int i = 0; i < 128; ++i) s = fmaf(h2[i], w3[(size_t)i * 64 + tid], s);
        h3[tid] = fmaxf(s, 0.f);
    }
    __syncthreads();
    if (tid < 2) {
        float s = b4[tid];
        for (int i = 0; i < 64; ++i) s = fmaf(h3[i], w4[(size_t)i * 2 + tid], s);
        out[tid] = (tid == 0) ? s : s * s;
    }
}

// ---------------- host launcher ----------------
extern "C" void kernel_launch(void* const* d_in, const int* in_sizes, int n_in,
                              void* d_out, int out_size) {
    const float* x0 = (const float*)d_in[0];
    const float* x1 = (const float*)d_in[1];
    const float* x2 = (const float*)d_in[2];
    const float* x3 = (const float*)d_in[3];
    const float* x4 = (const float*)d_in[4];
    const int*   rows = (const int*)d_in[5];
    const int*   cols = (const int*)d_in[6];
    const float* vals = (const float*)d_in[7];
    const float* gf   = (const float*)d_in[8];
    const float* Whmc = (const float*)d_in[9];
    const float* fc1w = (const float*)d_in[10];
    const float* fc1b = (const float*)d_in[11];
    const float* fc2w = (const float*)d_in[12];
    const float* fc2b = (const float*)d_in[13];
    const float* fc3w = (const float*)d_in[14];
    const float* fc3b = (const float*)d_in[15];
    const float* fc4w = (const float*)d_in[16];
    const float* fc4b = (const float*)d_in[17];
    float* out = (float*)d_out;

    const int SMEM_BYTES = 34816;
    cudaFuncSetAttribute(k_gemm, cudaFuncAttributeMaxDynamicSharedMemorySize,
                         SMEM_BYTES);

    int2* h_edge = nullptr;
    __half* h_Wh = nullptr;
    cudaGetSymbolAddress((void**)&h_edge, g_edge);
    cudaGetSymbolAddress((void**)&h_Wh, g_Wh);

    k_xh<<<4096, 256>>>((const float4*)x0, (const float4*)x1, (const float4*)x2,
                        (const float4*)x3, (const float4*)x4);
    k_prep<<<6329, 256>>>(rows, cols, vals);
    k_wconv<<<720, 256>>>(Whmc);

    const int AGG_BLOCKS = TOTAL_S / 40;   // 20250
    // L0: Xh -> Xh
    k_agg<<<AGG_BLOCKS, 256>>>(h_edge);
    k_gemm<<<2425, 256, SMEM_BYTES>>>(h_Wh,           0, 0, 1);
    // L1: Xh -> Xh
    k_agg<<<AGG_BLOCKS, 256>>>(h_edge);
    k_gemm<<<2425, 256, SMEM_BYTES>>>(h_Wh + 15*4096, 0, 0, 1);
    // L2: residual from Xh, fused pooling, no feature writes
    k_agg<<<AGG_BLOCKS, 256>>>(h_edge);
    k_pool_init<<<1, 320>>>();
    k_gemm<<<2425, 256, SMEM_BYTES>>>(h_Wh + 30*4096, 1, 1, 0);

    k_fc1<<<16, 256>>>(fc1w, fc1b, gf);
    k_tail<<<1, 128>>>(fc2w, fc2b, fc3w, fc3b, fc4w, fc4b, out);
}